// round 8
// baseline (speedup 1.0000x reference)
#include <cuda_runtime.h>
#include <cstdint>
#include <math.h>

#define T_TOK 8192
#define D_DIM 1024
#define F_DIM 2048
#define E_EXP 8
#define KSEL  2
#define CAP   4096

// within-row k-permutation: pairs (k, k+4) become adjacent words
#define PERM(k) (((k) & ~7) | (((k) & 3) << 1) | (((k) >> 2) & 1))

// ---------------- device scratch ----------------
__device__ float    g_H  [(size_t)E_EXP * CAP * F_DIM];   // permuted-F rows
__device__ float    g_Y  [(size_t)E_EXP * CAP * D_DIM];   // plain rows
__device__ uint32_t g_xt [(size_t)T_TOK * D_DIM];         // tf32(x), permuted-D rows
__device__ uint32_t g_wgt[(size_t)E_EXP * D_DIM * F_DIM]; // tf32(Wg), k-block layout
__device__ uint32_t g_wut[(size_t)E_EXP * D_DIM * F_DIM];
__device__ uint32_t g_wdt[(size_t)E_EXP * F_DIM * D_DIM];
__device__ int      g_cnt[E_EXP];
__device__ int      g_tok[E_EXP * CAP];
__device__ float    g_wt [E_EXP * CAP];
__device__ int      g_smap[T_TOK * KSEL];
__device__ double   g_psum[E_EXP];
__device__ double   g_zsum;

// ---------------- helpers ----------------
__device__ __forceinline__ uint32_t f2tf(float f) {
    uint32_t r;
    asm("cvt.rna.tf32.f32 %0, %1;" : "=r"(r) : "f"(f));
    return r;
}
__device__ __forceinline__ uint32_t s2u(const void* p) {
    uint32_t a;
    asm("{ .reg .u64 t; cvta.to.shared.u64 t, %1; cvt.u32.u64 %0, t; }" : "=r"(a) : "l"(p));
    return a;
}
#define CPA16(dst, src) \
    asm volatile("cp.async.cg.shared.global [%0], [%1], 16;" :: "r"((uint32_t)(dst)), "l"(src) : "memory")
#define CPCOMMIT() asm volatile("cp.async.commit_group;" ::: "memory")
#define CPWAITG(n) asm volatile("cp.async.wait_group %0;" :: "n"(n) : "memory")

__device__ __forceinline__ void mma8(float* d, const uint32_t* a, const uint32_t* b) {
    asm volatile("mma.sync.aligned.m16n8k8.row.col.f32.tf32.tf32.f32 "
                 "{%0,%1,%2,%3}, {%4,%5,%6,%7}, {%8,%9}, {%0,%1,%2,%3};"
                 : "+f"(d[0]), "+f"(d[1]), "+f"(d[2]), "+f"(d[3])
                 : "r"(a[0]), "r"(a[1]), "r"(a[2]), "r"(a[3]), "r"(b[0]), "r"(b[1]));
}

// SMEM geometry (words)
#define SAW 40                 // A row stride (32 used + 8 pad) -> LDS.64 conflict-free
#define ABYTES (128 * SAW * 4) // 20480
#define BQC 264                // B qc-row stride (256 used + 8 pad)
#define BBLK 1056              // B k8-block stride (4*264)
#define BBYTES (4 * BBLK * 4)  // 16896
#define STAGE1 (ABYTES + 2 * BBYTES)  // 54272
#define STAGE2 (ABYTES + BBYTES)      // 37376
#define BUF0   1024
#define NSTG   4
#define SMEM1  (BUF0 + NSTG * STAGE1) // 218112
#define SMEM2  (BUF0 + NSTG * STAGE2) // 150528

// ---------------- small kernels ----------------
__global__ void init_kernel() {
    int i = threadIdx.x;
    if (i < E_EXP) { g_cnt[i] = 0; g_psum[i] = 0.0; }
    if (i == 0) g_zsum = 0.0;
}

__global__ void cvt_all(const float* __restrict__ x, const float* __restrict__ wg,
                        const float* __restrict__ wu, const float* __restrict__ wd) {
    int stride = gridDim.x * blockDim.x;
    int i0 = blockIdx.x * blockDim.x + threadIdx.x;
    const int nx = T_TOK * D_DIM / 4;
    const int nw = E_EXP * D_DIM * F_DIM / 4;
    // x: per-row PERM over D
    for (int i = i0; i < nx; i += stride) {
        float4 v = ((const float4*)x)[i];
        int t = i >> 8;           // D/4 = 256
        int k0 = (i & 255) * 4;
        uint32_t* dst = g_xt + (size_t)t * D_DIM;
        dst[PERM(k0 + 0)] = f2tf(v.x);
        dst[PERM(k0 + 1)] = f2tf(v.y);
        dst[PERM(k0 + 2)] = f2tf(v.z);
        dst[PERM(k0 + 3)] = f2tf(v.w);
    }
    // Wg/Wu: [E][D][F], k-block layout: dst = (k>>3)*8F + (k&3)*2F + n*2 + ((k>>2)&1)
    for (int i = i0; i < nw; i += stride) {
        int R = i >> 9;               // F/4 = 512
        int n0 = (i & 511) * 4;
        int e = R >> 10;              // D = 1024 rows per expert
        int k = R & 1023;
        size_t base = (size_t)e * D_DIM * F_DIM
                    + (size_t)(k >> 3) * 8 * F_DIM + (k & 3) * 2 * F_DIM + ((k >> 2) & 1);
        float4 vg = ((const float4*)wg)[i];
        float4 vu = ((const float4*)wu)[i];
        g_wgt[base + (size_t)(n0 + 0) * 2] = f2tf(vg.x);
        g_wgt[base + (size_t)(n0 + 1) * 2] = f2tf(vg.y);
        g_wgt[base + (size_t)(n0 + 2) * 2] = f2tf(vg.z);
        g_wgt[base + (size_t)(n0 + 3) * 2] = f2tf(vg.w);
        g_wut[base + (size_t)(n0 + 0) * 2] = f2tf(vu.x);
        g_wut[base + (size_t)(n0 + 1) * 2] = f2tf(vu.y);
        g_wut[base + (size_t)(n0 + 2) * 2] = f2tf(vu.z);
        g_wut[base + (size_t)(n0 + 3) * 2] = f2tf(vu.w);
    }
    // Wd: [E][F][D]
    for (int i = i0; i < nw; i += stride) {
        int R = i >> 8;               // D/4 = 256
        int n0 = (i & 255) * 4;
        int e = R >> 11;              // F = 2048 rows per expert
        int k = R & 2047;
        size_t base = (size_t)e * F_DIM * D_DIM
                    + (size_t)(k >> 3) * 8 * D_DIM + (k & 3) * 2 * D_DIM + ((k >> 2) & 1);
        float4 v = ((const float4*)wd)[i];
        g_wdt[base + (size_t)(n0 + 0) * 2] = f2tf(v.x);
        g_wdt[base + (size_t)(n0 + 1) * 2] = f2tf(v.y);
        g_wdt[base + (size_t)(n0 + 2) * 2] = f2tf(v.z);
        g_wdt[base + (size_t)(n0 + 3) * 2] = f2tf(v.w);
    }
}

__global__ void router_kernel(const float* __restrict__ x,
                              const float* __restrict__ Wr) {
    __shared__ double s_ps[E_EXP];
    __shared__ double s_zs;
    int tid = threadIdx.x;
    if (tid < E_EXP) s_ps[tid] = 0.0;
    if (tid == 0) s_zs = 0.0;
    __syncthreads();
    int lane = tid & 31, warp = tid >> 5;
    int nw = (gridDim.x * blockDim.x) >> 5;
    int gw = blockIdx.x * (blockDim.x >> 5) + warp;
    double lps[E_EXP];
#pragma unroll
    for (int e = 0; e < E_EXP; e++) lps[e] = 0.0;
    double lzs = 0.0;
    for (int t = gw; t < T_TOK; t += nw) {
        const float* xr = x + (size_t)t * D_DIM;
        float acc[E_EXP];
#pragma unroll
        for (int e = 0; e < E_EXP; e++) acc[e] = 0.f;
        for (int i = lane; i < D_DIM; i += 32) {
            float xv = xr[i];
#pragma unroll
            for (int e = 0; e < E_EXP; e++)
                acc[e] = fmaf(xv, Wr[i * E_EXP + e], acc[e]);
        }
#pragma unroll
        for (int e = 0; e < E_EXP; e++)
#pragma unroll
            for (int o = 16; o > 0; o >>= 1)
                acc[e] += __shfl_xor_sync(0xffffffffu, acc[e], o);
        if (lane == 0) {
            float m = acc[0];
#pragma unroll
            for (int e = 1; e < E_EXP; e++) m = fmaxf(m, acc[e]);
            float s = 0.f, p[E_EXP];
#pragma unroll
            for (int e = 0; e < E_EXP; e++) { p[e] = expf(acc[e] - m); s += p[e]; }
            float inv = 1.f / s;
#pragma unroll
            for (int e = 0; e < E_EXP; e++) { p[e] *= inv; lps[e] += (double)p[e]; }
            float lse = m + logf(s);
            lzs += (double)lse * (double)lse;
            int i0 = 0; float v0 = acc[0];
#pragma unroll
            for (int e = 1; e < E_EXP; e++) if (acc[e] > v0) { v0 = acc[e]; i0 = e; }
            int i1 = -1; float v1 = -INFINITY;
#pragma unroll
            for (int e = 0; e < E_EXP; e++)
                if (e != i0 && acc[e] > v1) { v1 = acc[e]; i1 = e; }
            float rinv = 1.f / (p[i0] + p[i1]);
            int p0 = atomicAdd(&g_cnt[i0], 1);
            g_tok[i0 * CAP + p0] = t; g_wt[i0 * CAP + p0] = p[i0] * rinv;
            g_smap[t * 2 + 0] = i0 * CAP + p0;
            int p1 = atomicAdd(&g_cnt[i1], 1);
            g_tok[i1 * CAP + p1] = t; g_wt[i1 * CAP + p1] = p[i1] * rinv;
            g_smap[t * 2 + 1] = i1 * CAP + p1;
        }
    }
    if (lane == 0) {
#pragma unroll
        for (int e = 0; e < E_EXP; e++) atomicAdd(&s_ps[e], lps[e]);
        atomicAdd(&s_zs, lzs);
    }
    __syncthreads();
    if (tid < E_EXP) atomicAdd(&g_psum[tid], s_ps[tid]);
    if (tid == 0) atomicAdd(&g_zsum, s_zs);
}

__global__ void finalize_kernel(float* __restrict__ out, long long out_elems) {
    if (threadIdx.x == 0 && blockIdx.x == 0) {
        double lb = 0.0;
        for (int e = 0; e < E_EXP; e++)
            lb += ((double)g_cnt[e] / (double)(T_TOK * KSEL)) * (g_psum[e] / (double)T_TOK);
        lb *= (double)E_EXP;
        double aux = 0.01 * lb + 0.001 * (g_zsum / (double)T_TOK);
        long long idx = (long long)T_TOK * D_DIM;
        if (out_elems > idx) out[idx] = (float)aux;
    }
}

__global__ void combine_kernel(float* __restrict__ out) {
    int t = blockIdx.x;
    int d4 = threadIdx.x;
    int s0 = g_smap[t * 2 + 0], s1 = g_smap[t * 2 + 1];
    float w0 = g_wt[s0], w1 = g_wt[s1];
    float4 y0 = ((const float4*)g_Y)[(size_t)s0 * (D_DIM / 4) + d4];
    float4 y1 = ((const float4*)g_Y)[(size_t)s1 * (D_DIM / 4) + d4];
    float4 r;
    r.x = w0 * y0.x + w1 * y1.x;
    r.y = w0 * y0.y + w1 * y1.y;
    r.z = w0 * y0.z + w1 * y1.z;
    r.w = w0 * y0.w + w1 * y1.w;
    ((float4*)out)[(size_t)t * (D_DIM / 4) + d4] = r;
}

// ---------------- GEMM1: 256 thr, warp grid 2x4 (64x32 tiles), 4-stage ----------------
__global__ __launch_bounds__(256, 1)
void gemm1_mma(const float* dummy) {
    int e = blockIdx.z;
    int n = g_cnt[e];
    int row0 = blockIdx.y * 128;
    if (row0 >= n) return;
    int col0 = blockIdx.x * 128;

    extern __shared__ char smem[];
    int* toks = (int*)smem;
    uint32_t sb = s2u(smem);
    int tid = threadIdx.x, wid = tid >> 5, l = tid & 31;

    if (tid < 128) {
        int r = row0 + tid;
        toks[tid] = (r < n) ? g_tok[e * CAP + r] : g_tok[e * CAP];
    }
    __syncthreads();

    // A fill: 2 threads/row, 4 chunks each (16 words)
    int arow = tid >> 1, ahalf = tid & 1;
    int tok = toks[arow];
    const uint32_t* srcA = g_xt + (size_t)tok * D_DIM + ahalf * 16;
    uint32_t adst[4];
#pragma unroll
    for (int j = 0; j < 4; j++)
        adst[j] = (uint32_t)((arow * SAW + ahalf * 16 + j * 4) * 4);

    // B fill: (bblk, bqc, 4 consecutive m)
    int bblk = tid >> 6, bqc = (tid >> 4) & 3, bm0 = (tid & 15) * 4;
    size_t bsrcoff = (size_t)bblk * 8 * F_DIM + (size_t)bqc * 2 * F_DIM + (size_t)col0 * 2 + bm0 * 4;
    const uint32_t* srcG = g_wgt + (size_t)e * D_DIM * F_DIM + bsrcoff;
    const uint32_t* srcU = g_wut + (size_t)e * D_DIM * F_DIM + bsrcoff;
    uint32_t bdst[4];
#pragma unroll
    for (int j = 0; j < 4; j++)
        bdst[j] = (uint32_t)((bblk * BBLK + bqc * BQC + (bm0 + j) * 4) * 4);

    const int NT = D_DIM / 32;  // 32

#define G1_ISSUE(c, slot) do { \
    uint32_t base_ = sb + BUF0 + (slot) * STAGE1; \
    const uint32_t* sa_ = srcA + (c) * 32; \
    const uint32_t* sg_ = srcG + (size_t)(c) * 32 * F_DIM; \
    const uint32_t* su_ = srcU + (size_t)(c) * 32 * F_DIM; \
    CPA16(base_ + adst[0], sa_); \
    CPA16(base_ + adst[1], sa_ + 4); \
    CPA16(base_ + adst[2], sa_ + 8); \
    CPA16(base_ + adst[3], sa_ + 12); \
    CPA16(base_ + ABYTES + bdst[0], sg_); \
    CPA16(base_ + ABYTES + bdst[1], sg_ + 4); \
    CPA16(base_ + ABYTES + bdst[2], sg_ + 8); \
    CPA16(base_ + ABYTES + bdst[3], sg_ + 12); \
    CPA16(base_ + ABYTES + BBYTES + bdst[0], su_); \
    CPA16(base_ + ABYTES + BBYTES + bdst[1], su_ + 4); \
    CPA16(base_ + ABYTES + BBYTES + bdst[2], su_ + 8); \
    CPA16(base_ + ABYTES + BBYTES + bdst[3], su_ + 12); \
} while (0)

    float accG[4][4][4] = {}, accU[4][4][4] = {};
    int wm = wid & 1, wn = wid >> 1;
    int qr = l >> 2, qc = l & 3;

    G1_ISSUE(0, 0); CPCOMMIT();
    G1_ISSUE(1, 1); CPCOMMIT();
    G1_ISSUE(2, 2); CPCOMMIT();

    int slot = 0;
#pragma unroll 1
    for (int c = 0; c < NT; c++) {
        CPWAITG(2);
        __syncthreads();
        const uint32_t* As = (const uint32_t*)(smem + BUF0 + slot * STAGE1);
        const uint32_t* Gs = As + ABYTES / 4;
        const uint32_t* Us = As + (ABYTES + BBYTES) / 4;
#pragma unroll
        for (int ks = 0; ks < 4; ks++) {
            uint32_t af[4][4];
#pragma unroll
            for (int mt = 0; mt < 4; mt++) {
                int r0 = wm * 64 + mt * 16 + qr;
                uint2 lo = *(const uint2*)&As[r0 * SAW + ks * 8 + qc * 2];
                uint2 hi = *(const uint2*)&As[(r0 + 8) * SAW + ks * 8 + qc * 2];
                af[mt][0] = lo.x; af[mt][1] = hi.x; af[mt][2] = lo.y; af[mt][3] = hi.y;
            }
            uint32_t bg[4][2], bu[4][2];
#pragma unroll
            for (int nt = 0; nt < 4; nt++) {
                int cc = wn * 32 + nt * 8 + qr;
                uint2 g2 = *(const uint2*)&Gs[ks * BBLK + qc * BQC + cc * 2];
                uint2 u2 = *(const uint2*)&Us[ks * BBLK + qc * BQC + cc * 2];
                bg[nt][0] = g2.x; bg[nt][1] = g2.y;
                bu[nt][0] = u2.x; bu[nt][1] = u2.y;
            }
#pragma unroll
            for (int mt = 0; mt < 4; mt++)
#pragma unroll
                for (int nt = 0; nt < 4; nt++) {
                    mma8(accG[mt][nt], af[mt], bg[nt]);
                    mma8(accU[mt][nt], af[mt], bu[nt]);
                }
        }
        if (c + 3 < NT) {
            int ws = slot + 3; if (ws >= NSTG) ws -= NSTG;
            G1_ISSUE(c + 3, ws);
        }
        CPCOMMIT();
        if (++slot == NSTG) slot = 0;
    }

    // epilogue: SwiGLU -> g_H (tf32-rounded), PERMUTED F layout
#pragma unroll
    for (int mt = 0; mt < 4; mt++)
#pragma unroll
        for (int half = 0; half < 2; half++) {
            int grow = row0 + wm * 64 + mt * 16 + qr + half * 8;
            if (grow < n) {
                float* hrow = &g_H[((size_t)e * CAP + grow) * F_DIM];
#pragma unroll
                for (int nt = 0; nt < 4; nt++) {
                    int f0 = col0 + wn * 32 + nt * 8 + qc * 2;
                    float g0 = accG[mt][nt][half * 2], g1 = accG[mt][nt][half * 2 + 1];
                    float u0 = accU[mt][nt][half * 2], u1 = accU[mt][nt][half * 2 + 1];
                    hrow[PERM(f0)]     = __uint_as_float(f2tf(g0 / (1.f + expf(-g0)) * u0));
                    hrow[PERM(f0 + 1)] = __uint_as_float(f2tf(g1 / (1.f + expf(-g1)) * u1));
                }
            }
        }
}

// ---------------- GEMM2: Y[slot] = H[slot] @ Wd — 4-stage ----------------
__global__ __launch_bounds__(256, 1)
void gemm2_mma(const float* dummy) {
    int e = blockIdx.z;
    int n = g_cnt[e];
    int row0 = blockIdx.y * 128;
    if (row0 >= n) return;
    int col0 = blockIdx.x * 128;

    extern __shared__ char smem[];
    uint32_t sb = s2u(smem);
    int tid = threadIdx.x, wid = tid >> 5, l = tid & 31;

    int arow = tid >> 1, ahalf = tid & 1;
    int hr = (row0 + arow < n) ? (row0 + arow) : 0;
    const uint32_t* srcA = (const uint32_t*)g_H + ((size_t)e * CAP + hr) * F_DIM + ahalf * 16;
    int bblk = tid >> 6, bqc = (tid >> 4) & 3, bm0 = (tid & 15) * 4;
    const uint32_t* srcB = g_wdt + (size_t)e * F_DIM * D_DIM
                         + (size_t)bblk * 8 * D_DIM + (size_t)bqc * 2 * D_DIM
                         + (size_t)col0 * 2 + bm0 * 4;
    uint32_t adst[4], bdst[4];
#pragma unroll
    for (int j = 0; j < 4; j++) {
        adst[j] = (uint32_t)((arow * SAW + ahalf * 16 + j * 4) * 4);
        bdst[j] = (uint32_t)((bblk * BBLK + bqc * BQC + (bm0 + j) * 4) * 4);
    }

    const int NT = F_DIM / 32;  // 64

#define G2_ISSUE(c, slot) do { \
    uint32_t base_ = sb + BUF0 + (slot) * STAGE2; \
    const uint32_t* sa_ = srcA + (c) * 32; \
    const uint32_t* sb_ = srcB + (size_t)(c) * 32 * D_DIM; \
    CPA16(base_ + adst[0], sa_); \
    CPA16(base_ + adst[1], sa_ + 4); \
    CPA16(base_ + adst[2], sa_ + 8); \
    CPA16(base_ + adst[3], sa_ + 12); \
    CPA16(base_ + ABYTES + bdst[0], sb_); \
    CPA16(base_ + ABYTES + bdst[1], sb_ + 4); \
    CPA16(base_ + ABYTES + bdst[2], sb_ + 8); \
    CPA16(base_ + ABYTES + bdst[3], sb_ + 12); \
} while (0)

    float acc[4][4][4] = {};
    int wm = wid & 1, wn = wid >> 1;
    int qr = l >> 2, qc = l & 3;

    G2_ISSUE(0, 0); CPCOMMIT();
    G2_ISSUE(1, 1); CPCOMMIT();
    G2_ISSUE(2, 2); CPCOMMIT();

    int slot = 0;
#pragma unroll 1
    for (int c = 0; c < NT; c++) {
        CPWAITG(2);
        __syncthreads();
        const uint32_t* As = (const uint32_t*)(smem + BUF0 + slot * STAGE2);
        const uint32_t* Bs = As + ABYTES / 4;
#pragma unroll
        for (int ks = 0; ks < 4; ks++) {
            uint32_t af[4][4];
#pragma unroll
            for (int mt = 0; mt < 4; mt++) {
                int r0 = wm * 64 + mt * 16 + qr;
                uint2 lo = *(const uint2*)&As[r0 * SAW + ks * 8 + qc * 2];
                uint2 hi = *(const uint2*)&As[(r0 + 8) * SAW + ks * 8 + qc * 2];
                af[mt][0] = lo.x; af[mt][1] = hi.x; af[mt][2] = lo.y; af[mt][3] = hi.y;
            }
            uint32_t bf[4][2];
#pragma unroll
            for (int nt = 0; nt < 4; nt++) {
                int cc = wn * 32 + nt * 8 + qr;
                uint2 b2 = *(const uint2*)&Bs[ks * BBLK + qc * BQC + cc * 2];
                bf[nt][0] = b2.x; bf[nt][1] = b2.y;
            }
#pragma unroll
            for (int mt = 0; mt < 4; mt++)
#pragma unroll
                for (int nt = 0; nt < 4; nt++)
                    mma8(acc[mt][nt], af[mt], bf[nt]);
        }
        if (c + 3 < NT) {
            int ws = slot + 3; if (ws >= NSTG) ws -= NSTG;
            G2_ISSUE(c + 3, ws);
        }
        CPCOMMIT();
        if (++slot == NSTG) slot = 0;
    }

    // epilogue: plain stores (g_Y rows are linear)
#pragma unroll
    for (int mt = 0; mt < 4; mt++)
#pragma unroll
        for (int half = 0; half < 2; half++) {
            int grow = row0 + wm * 64 + mt * 16 + qr + half * 8;
            if (grow < n) {
                float* yrow = &g_Y[((size_t)e * CAP + grow) * D_DIM + col0];
#pragma unroll
                for (int nt = 0; nt < 4; nt++) {
                    float v0 = acc[mt][nt][half * 2];
                    float v1 = acc[mt][nt][half * 2 + 1];
                    *(float2*)(yrow + wn * 32 + nt * 8 + qc * 2) = make_float2(v0, v1);
                }
            }
        }
}

// ---------------- launch ----------------
extern "C" void kernel_launch(void* const* d_in, const int* in_sizes, int n_in,
                              void* d_out, int out_size) {
    const float* x  = (const float*)d_in[0];
    const float* Wr = (const float*)d_in[1];
    const float* Wg = (const float*)d_in[2];
    const float* Wu = (const float*)d_in[3];
    const float* Wd = (const float*)d_in[4];
    float* out = (float*)d_out;

    cudaFuncSetAttribute(gemm1_mma, cudaFuncAttributeMaxDynamicSharedMemorySize, SMEM1);
    cudaFuncSetAttribute(gemm2_mma, cudaFuncAttributeMaxDynamicSharedMemorySize, SMEM2);

    init_kernel<<<1, 32>>>();
    cvt_all<<<2048, 256>>>(x, Wg, Wu, Wd);
    router_kernel<<<128, 256>>>(x, Wr);
    dim3 g1(F_DIM / 128, CAP / 128, E_EXP);
    gemm1_mma<<<g1, 256, SMEM1>>>(x);
    dim3 g2(D_DIM / 128, CAP / 128, E_EXP);
    gemm2_mma<<<g2, 256, SMEM2>>>(x);
    combine_kernel<<<T_TOK, D_DIM / 4>>>(out);
    finalize_kernel<<<1, 32>>>(out, (long long)out_size);
}

// round 9
// speedup vs baseline: 1.1568x; 1.1568x over previous
#include <cuda_runtime.h>
#include <cstdint>
#include <math.h>

#define T_TOK 8192
#define D_DIM 1024
#define F_DIM 2048
#define E_EXP 8
#define KSEL  2
#define CAP   4096

// ---------------- device scratch ----------------
__device__ float    g_H  [(size_t)E_EXP * CAP * F_DIM];   // G raw, then H (tf32 bits)
__device__ float    g_Y  [(size_t)E_EXP * CAP * D_DIM];
__device__ uint32_t g_xt [(size_t)T_TOK * D_DIM];
__device__ uint32_t g_wgt[(size_t)E_EXP * D_DIM * F_DIM];
__device__ uint32_t g_wut[(size_t)E_EXP * D_DIM * F_DIM];
__device__ uint32_t g_wdt[(size_t)E_EXP * F_DIM * D_DIM];
__device__ int      g_cnt[E_EXP];
__device__ int      g_tok[E_EXP * CAP];
__device__ float    g_wt [E_EXP * CAP];
__device__ int      g_smap[T_TOK * KSEL];
__device__ double   g_psum[E_EXP];
__device__ double   g_zsum;

// ---------------- helpers ----------------
__device__ __forceinline__ uint32_t f2tf(float f) {
    uint32_t r;
    asm("cvt.rna.tf32.f32 %0, %1;" : "=r"(r) : "f"(f));
    return r;
}
__device__ __forceinline__ uint32_t s2u(const void* p) {
    uint32_t a;
    asm("{ .reg .u64 t; cvta.to.shared.u64 t, %1; cvt.u32.u64 %0, t; }" : "=r"(a) : "l"(p));
    return a;
}
#define CPA16(dst, src) \
    asm volatile("cp.async.cg.shared.global [%0], [%1], 16;" :: "r"((uint32_t)(dst)), "l"(src) : "memory")
#define CPCOMMIT() asm volatile("cp.async.commit_group;" ::: "memory")
#define CPWAITG(n) asm volatile("cp.async.wait_group %0;" :: "n"(n) : "memory")

__device__ __forceinline__ void mma8(float* d, const uint32_t* a, const uint32_t* b) {
    asm volatile("mma.sync.aligned.m16n8k8.row.col.f32.tf32.tf32.f32 "
                 "{%0,%1,%2,%3}, {%4,%5,%6,%7}, {%8,%9}, {%0,%1,%2,%3};"
                 : "+f"(d[0]), "+f"(d[1]), "+f"(d[2]), "+f"(d[3])
                 : "r"(a[0]), "r"(a[1]), "r"(a[2]), "r"(a[3]), "r"(b[0]), "r"(b[1]));
}

// SMEM (words) — R7 proven layout
#define SA 36
#define SB 132
#define ABYTES (128 * SA * 4)          // 18432
#define BBYTES (32 * SB * 4)           // 16896
#define STAGE  (ABYTES + BBYTES)       // 35328
#define BUF0   1024
#define NSTG   3
#define SMEMSZ (BUF0 + NSTG * STAGE)   // 107008  (x2 CTAs = 214KB <= 228KB/SM)

// ---------------- small kernels ----------------
__global__ void init_kernel() {
    int i = threadIdx.x;
    if (i < E_EXP) { g_cnt[i] = 0; g_psum[i] = 0.0; }
    if (i == 0) g_zsum = 0.0;
}

__global__ void cvt_all(const float* __restrict__ x, const float* __restrict__ wg,
                        const float* __restrict__ wu, const float* __restrict__ wd) {
    int stride = gridDim.x * blockDim.x;
    int i0 = blockIdx.x * blockDim.x + threadIdx.x;
    const int nx = T_TOK * D_DIM / 4;
    const int nw = E_EXP * D_DIM * F_DIM / 4;
    for (int i = i0; i < nx; i += stride) {
        float4 v = ((const float4*)x)[i];
        ((uint4*)g_xt)[i] = make_uint4(f2tf(v.x), f2tf(v.y), f2tf(v.z), f2tf(v.w));
    }
    for (int i = i0; i < nw; i += stride) {
        float4 v = ((const float4*)wg)[i];
        ((uint4*)g_wgt)[i] = make_uint4(f2tf(v.x), f2tf(v.y), f2tf(v.z), f2tf(v.w));
    }
    for (int i = i0; i < nw; i += stride) {
        float4 v = ((const float4*)wu)[i];
        ((uint4*)g_wut)[i] = make_uint4(f2tf(v.x), f2tf(v.y), f2tf(v.z), f2tf(v.w));
    }
    for (int i = i0; i < nw; i += stride) {
        float4 v = ((const float4*)wd)[i];
        ((uint4*)g_wdt)[i] = make_uint4(f2tf(v.x), f2tf(v.y), f2tf(v.z), f2tf(v.w));
    }
}

__global__ void router_kernel(const float* __restrict__ x,
                              const float* __restrict__ Wr) {
    __shared__ double s_ps[E_EXP];
    __shared__ double s_zs;
    int tid = threadIdx.x;
    if (tid < E_EXP) s_ps[tid] = 0.0;
    if (tid == 0) s_zs = 0.0;
    __syncthreads();
    int lane = tid & 31, warp = tid >> 5;
    int nw = (gridDim.x * blockDim.x) >> 5;
    int gw = blockIdx.x * (blockDim.x >> 5) + warp;
    double lps[E_EXP];
#pragma unroll
    for (int e = 0; e < E_EXP; e++) lps[e] = 0.0;
    double lzs = 0.0;
    for (int t = gw; t < T_TOK; t += nw) {
        const float* xr = x + (size_t)t * D_DIM;
        float acc[E_EXP];
#pragma unroll
        for (int e = 0; e < E_EXP; e++) acc[e] = 0.f;
        for (int i = lane; i < D_DIM; i += 32) {
            float xv = xr[i];
#pragma unroll
            for (int e = 0; e < E_EXP; e++)
                acc[e] = fmaf(xv, Wr[i * E_EXP + e], acc[e]);
        }
#pragma unroll
        for (int e = 0; e < E_EXP; e++)
#pragma unroll
            for (int o = 16; o > 0; o >>= 1)
                acc[e] += __shfl_xor_sync(0xffffffffu, acc[e], o);
        if (lane == 0) {
            float m = acc[0];
#pragma unroll
            for (int e = 1; e < E_EXP; e++) m = fmaxf(m, acc[e]);
            float s = 0.f, p[E_EXP];
#pragma unroll
            for (int e = 0; e < E_EXP; e++) { p[e] = expf(acc[e] - m); s += p[e]; }
            float inv = 1.f / s;
#pragma unroll
            for (int e = 0; e < E_EXP; e++) { p[e] *= inv; lps[e] += (double)p[e]; }
            float lse = m + logf(s);
            lzs += (double)lse * (double)lse;
            int i0 = 0; float v0 = acc[0];
#pragma unroll
            for (int e = 1; e < E_EXP; e++) if (acc[e] > v0) { v0 = acc[e]; i0 = e; }
            int i1 = -1; float v1 = -INFINITY;
#pragma unroll
            for (int e = 0; e < E_EXP; e++)
                if (e != i0 && acc[e] > v1) { v1 = acc[e]; i1 = e; }
            float rinv = 1.f / (p[i0] + p[i1]);
            int p0 = atomicAdd(&g_cnt[i0], 1);
            g_tok[i0 * CAP + p0] = t; g_wt[i0 * CAP + p0] = p[i0] * rinv;
            g_smap[t * 2 + 0] = i0 * CAP + p0;
            int p1 = atomicAdd(&g_cnt[i1], 1);
            g_tok[i1 * CAP + p1] = t; g_wt[i1 * CAP + p1] = p[i1] * rinv;
            g_smap[t * 2 + 1] = i1 * CAP + p1;
        }
    }
    if (lane == 0) {
#pragma unroll
        for (int e = 0; e < E_EXP; e++) atomicAdd(&s_ps[e], lps[e]);
        atomicAdd(&s_zs, lzs);
    }
    __syncthreads();
    if (tid < E_EXP) atomicAdd(&g_psum[tid], s_ps[tid]);
    if (tid == 0) atomicAdd(&g_zsum, s_zs);
}

__global__ void finalize_kernel(float* __restrict__ out, long long out_elems) {
    if (threadIdx.x == 0 && blockIdx.x == 0) {
        double lb = 0.0;
        for (int e = 0; e < E_EXP; e++)
            lb += ((double)g_cnt[e] / (double)(T_TOK * KSEL)) * (g_psum[e] / (double)T_TOK);
        lb *= (double)E_EXP;
        double aux = 0.01 * lb + 0.001 * (g_zsum / (double)T_TOK);
        long long idx = (long long)T_TOK * D_DIM;
        if (out_elems > idx) out[idx] = (float)aux;
    }
}

__global__ void combine_kernel(float* __restrict__ out) {
    int t = blockIdx.x;
    int d4 = threadIdx.x;
    int s0 = g_smap[t * 2 + 0], s1 = g_smap[t * 2 + 1];
    float w0 = g_wt[s0], w1 = g_wt[s1];
    float4 y0 = ((const float4*)g_Y)[(size_t)s0 * (D_DIM / 4) + d4];
    float4 y1 = ((const float4*)g_Y)[(size_t)s1 * (D_DIM / 4) + d4];
    float4 r;
    r.x = w0 * y0.x + w1 * y1.x;
    r.y = w0 * y0.y + w1 * y1.y;
    r.z = w0 * y0.z + w1 * y1.z;
    r.w = w0 * y0.w + w1 * y1.w;
    ((float4*)out)[(size_t)t * (D_DIM / 4) + d4] = r;
}

// ---------------- unified GEMM pass ----------------
// MODE 0: G = X@Wg          -> g_H raw
// MODE 1: U = X@Wu, swiglu with G from g_H -> g_H (tf32 bits)
// MODE 2: Y = H@Wd          -> g_Y raw
template<int MODE, int KDIM, int NCOLS>
__global__ __launch_bounds__(256, 2)
void gemm_pass(const uint32_t* __restrict__ Bw) {
    int e = blockIdx.z;
    int n = g_cnt[e];
    int row0 = blockIdx.y * 128;
    if (row0 >= n) return;
    int col0 = blockIdx.x * 128;

    extern __shared__ char smem[];
    int* toks = (int*)smem;
    uint32_t sb = s2u(smem);
    int tid = threadIdx.x, wid = tid >> 5, l = tid & 31;

    if (MODE < 2) {
        if (tid < 128) {
            int r = row0 + tid;
            toks[tid] = (r < n) ? g_tok[e * CAP + r] : g_tok[e * CAP];
        }
        __syncthreads();
    }

    int arow = tid >> 1, aseg0 = (tid & 1) * 4;
    const uint32_t* srcA;
    if (MODE < 2) {
        srcA = g_xt + (size_t)toks[arow] * D_DIM + aseg0 * 4;
    } else {
        int hr = (row0 + arow < n) ? (row0 + arow) : 0;
        srcA = (const uint32_t*)g_H + ((size_t)e * CAP + hr) * F_DIM + aseg0 * 4;
    }
    int brow = tid >> 3, bseg = tid & 7;
    const uint32_t* srcB = Bw + (size_t)e * KDIM * NCOLS + (size_t)brow * NCOLS + col0 + bseg * 4;
    uint32_t adst[4], bdst[4];
#pragma unroll
    for (int j = 0; j < 4; j++) {
        adst[j] = (uint32_t)((arow * SA + (aseg0 + j) * 4) * 4);
        bdst[j] = (uint32_t)((brow * SB + bseg * 4 + j * 32) * 4);
    }

    const int NT = KDIM / 32;

#define GP_ISSUE(c, slot) do { \
    uint32_t base_ = sb + BUF0 + (slot) * STAGE; \
    const uint32_t* sa_ = srcA + (c) * 32; \
    const uint32_t* sb_ = srcB + (size_t)(c) * 32 * NCOLS; \
    CPA16(base_ + adst[0], sa_); \
    CPA16(base_ + adst[1], sa_ + 4); \
    CPA16(base_ + adst[2], sa_ + 8); \
    CPA16(base_ + adst[3], sa_ + 12); \
    CPA16(base_ + ABYTES + bdst[0], sb_); \
    CPA16(base_ + ABYTES + bdst[1], sb_ + 32); \
    CPA16(base_ + ABYTES + bdst[2], sb_ + 64); \
    CPA16(base_ + ABYTES + bdst[3], sb_ + 96); \
} while (0)

    float acc[4][4][4] = {};
    int wm = wid & 1, wn = wid >> 1;
    int qr = l >> 2, qc = l & 3;

    GP_ISSUE(0, 0); CPCOMMIT();
    GP_ISSUE(1, 1); CPCOMMIT();

    int slot = 0;
#pragma unroll 1
    for (int c = 0; c < NT; c++) {
        CPWAITG(1);
        __syncthreads();
        const uint32_t* As = (const uint32_t*)(smem + BUF0 + slot * STAGE);
        const uint32_t* Bs = As + ABYTES / 4;
#pragma unroll
        for (int ks = 0; ks < 4; ks++) {
            int kk = ks * 8;
            uint32_t af[4][4];
#pragma unroll
            for (int mt = 0; mt < 4; mt++) {
                int r0 = wm * 64 + mt * 16 + qr;
                af[mt][0] = As[r0 * SA + kk + qc];
                af[mt][1] = As[(r0 + 8) * SA + kk + qc];
                af[mt][2] = As[r0 * SA + kk + qc + 4];
                af[mt][3] = As[(r0 + 8) * SA + kk + qc + 4];
            }
            uint32_t bf[4][2];
#pragma unroll
            for (int nt = 0; nt < 4; nt++) {
                int cc = wn * 32 + nt * 8 + qr;
                bf[nt][0] = Bs[(kk + qc) * SB + cc];
                bf[nt][1] = Bs[(kk + qc + 4) * SB + cc];
            }
#pragma unroll
            for (int mt = 0; mt < 4; mt++)
#pragma unroll
                for (int nt = 0; nt < 4; nt++)
                    mma8(acc[mt][nt], af[mt], bf[nt]);
        }
        if (c + 2 < NT) {
            int ws = slot + 2; if (ws >= NSTG) ws -= NSTG;
            GP_ISSUE(c + 2, ws);
        }
        CPCOMMIT();
        if (++slot == NSTG) slot = 0;
    }

    // epilogue
#pragma unroll
    for (int mt = 0; mt < 4; mt++)
#pragma unroll
        for (int half = 0; half < 2; half++) {
            int grow = row0 + wm * 64 + mt * 16 + qr + half * 8;
            if (grow < n) {
                if (MODE == 0) {
                    float* hrow = &g_H[((size_t)e * CAP + grow) * F_DIM + col0];
#pragma unroll
                    for (int nt = 0; nt < 4; nt++)
                        *(float2*)(hrow + wn * 32 + nt * 8 + qc * 2) =
                            make_float2(acc[mt][nt][half * 2], acc[mt][nt][half * 2 + 1]);
                } else if (MODE == 1) {
                    float* hrow = &g_H[((size_t)e * CAP + grow) * F_DIM + col0];
#pragma unroll
                    for (int nt = 0; nt < 4; nt++) {
                        float* hp = hrow + wn * 32 + nt * 8 + qc * 2;
                        float2 gv = *(float2*)hp;
                        float u0 = acc[mt][nt][half * 2], u1 = acc[mt][nt][half * 2 + 1];
                        float h0 = __uint_as_float(f2tf(gv.x / (1.f + expf(-gv.x)) * u0));
                        float h1 = __uint_as_float(f2tf(gv.y / (1.f + expf(-gv.y)) * u1));
                        *(float2*)hp = make_float2(h0, h1);
                    }
                } else {
                    float* yrow = &g_Y[((size_t)e * CAP + grow) * D_DIM + col0];
#pragma unroll
                    for (int nt = 0; nt < 4; nt++)
                        *(float2*)(yrow + wn * 32 + nt * 8 + qc * 2) =
                            make_float2(acc[mt][nt][half * 2], acc[mt][nt][half * 2 + 1]);
                }
            }
        }
}

// ---------------- launch ----------------
extern "C" void kernel_launch(void* const* d_in, const int* in_sizes, int n_in,
                              void* d_out, int out_size) {
    const float* x  = (const float*)d_in[0];
    const float* Wr = (const float*)d_in[1];
    const float* Wg = (const float*)d_in[2];
    const float* Wu = (const float*)d_in[3];
    const float* Wd = (const float*)d_in[4];
    float* out = (float*)d_out;

    uint32_t* wgt; cudaGetSymbolAddress((void**)&wgt, g_wgt);
    uint32_t* wut; cudaGetSymbolAddress((void**)&wut, g_wut);
    uint32_t* wdt; cudaGetSymbolAddress((void**)&wdt, g_wdt);

    cudaFuncSetAttribute((const void*)gemm_pass<0, D_DIM, F_DIM>,
                         cudaFuncAttributeMaxDynamicSharedMemorySize, SMEMSZ);
    cudaFuncSetAttribute((const void*)gemm_pass<1, D_DIM, F_DIM>,
                         cudaFuncAttributeMaxDynamicSharedMemorySize, SMEMSZ);
    cudaFuncSetAttribute((const void*)gemm_pass<2, F_DIM, D_DIM>,
                         cudaFuncAttributeMaxDynamicSharedMemorySize, SMEMSZ);

    init_kernel<<<1, 32>>>();
    cvt_all<<<2048, 256>>>(x, Wg, Wu, Wd);
    router_kernel<<<128, 256>>>(x, Wr);
    dim3 gG(F_DIM / 128, CAP / 128, E_EXP);
    gemm_pass<0, D_DIM, F_DIM><<<gG, 256, SMEMSZ>>>(wgt);
    gemm_pass<1, D_DIM, F_DIM><<<gG, 256, SMEMSZ>>>(wut);
    dim3 gD(D_DIM / 128, CAP / 128, E_EXP);
    gemm_pass<2, F_DIM, D_DIM><<<gD, 256, SMEMSZ>>>(wdt);
    combine_kernel<<<T_TOK, D_DIM / 4>>>(out);
    finalize_kernel<<<1, 32>>>(out, (long long)out_size);
}

// round 10
// speedup vs baseline: 1.4085x; 1.2176x over previous
#include <cuda_runtime.h>
#include <cstdint>
#include <math.h>

#define T_TOK 8192
#define D_DIM 1024
#define F_DIM 2048
#define E_EXP 8
#define KSEL  2
#define CAP   4096

// ---------------- device scratch ----------------
__device__ float    g_H  [(size_t)E_EXP * CAP * F_DIM];
__device__ float    g_Y  [(size_t)E_EXP * CAP * D_DIM];
__device__ uint32_t g_xt [(size_t)T_TOK * D_DIM];
__device__ uint32_t g_wgt[(size_t)E_EXP * D_DIM * F_DIM];
__device__ uint32_t g_wut[(size_t)E_EXP * D_DIM * F_DIM];
__device__ uint32_t g_wdt[(size_t)E_EXP * F_DIM * D_DIM];
__device__ int      g_cnt[E_EXP];
__device__ int      g_tok[E_EXP * CAP];
__device__ float    g_wt [E_EXP * CAP];
__device__ int      g_smap[T_TOK * KSEL];
__device__ double   g_psum[E_EXP];
__device__ double   g_zsum;

// ---------------- helpers ----------------
__device__ __forceinline__ uint32_t f2tf(float f) {
    uint32_t r;
    asm("cvt.rna.tf32.f32 %0, %1;" : "=r"(r) : "f"(f));
    return r;
}
__device__ __forceinline__ uint32_t s2u(const void* p) {
    uint32_t a;
    asm("{ .reg .u64 t; cvta.to.shared.u64 t, %1; cvt.u32.u64 %0, t; }" : "=r"(a) : "l"(p));
    return a;
}
#define CPA16(dst, src) \
    asm volatile("cp.async.cg.shared.global [%0], [%1], 16;" :: "r"((uint32_t)(dst)), "l"(src) : "memory")
#define CPCOMMIT() asm volatile("cp.async.commit_group;" ::: "memory")
#define CPWAITG(n) asm volatile("cp.async.wait_group %0;" :: "n"(n) : "memory")

__device__ __forceinline__ void mma8(float* d, const uint32_t* a, const uint32_t* b) {
    asm volatile("mma.sync.aligned.m16n8k8.row.col.f32.tf32.tf32.f32 "
                 "{%0,%1,%2,%3}, {%4,%5,%6,%7}, {%8,%9}, {%0,%1,%2,%3};"
                 : "+f"(d[0]), "+f"(d[1]), "+f"(d[2]), "+f"(d[3])
                 : "r"(a[0]), "r"(a[1]), "r"(a[2]), "r"(a[3]), "r"(b[0]), "r"(b[1]));
}

// SMEM strides (words) — SB=136 makes B fragment loads bank-conflict-free:
// bank((kk+qc)*136 + cc) = (8*qc + qr + const) mod 32 -> 32 distinct lanes.
#define SA 36
#define SB 136
#define ABYTES (128 * SA * 4)          // 18432
#define BBYTES (32 * SB * 4)           // 17408
#define STAGE1 (ABYTES + 2 * BBYTES)   // 53248
#define STAGE2 (ABYTES + BBYTES)       // 35840
#define BUF0   1024
#define NSTG   3
#define SMEM1  (BUF0 + NSTG * STAGE1)  // 160768
#define SMEM2  (BUF0 + NSTG * STAGE2)  // 108544

// ---------------- small kernels ----------------
__global__ void init_kernel() {
    int i = threadIdx.x;
    if (i < E_EXP) { g_cnt[i] = 0; g_psum[i] = 0.0; }
    if (i == 0) g_zsum = 0.0;
}

__global__ void cvt_all(const float* __restrict__ x, const float* __restrict__ wg,
                        const float* __restrict__ wu, const float* __restrict__ wd) {
    int stride = gridDim.x * blockDim.x;
    int i0 = blockIdx.x * blockDim.x + threadIdx.x;
    const int nx = T_TOK * D_DIM / 4;
    const int nw = E_EXP * D_DIM * F_DIM / 4;
    for (int i = i0; i < nx; i += stride) {
        float4 v = ((const float4*)x)[i];
        ((uint4*)g_xt)[i] = make_uint4(f2tf(v.x), f2tf(v.y), f2tf(v.z), f2tf(v.w));
    }
    for (int i = i0; i < nw; i += stride) {
        float4 v = ((const float4*)wg)[i];
        ((uint4*)g_wgt)[i] = make_uint4(f2tf(v.x), f2tf(v.y), f2tf(v.z), f2tf(v.w));
    }
    for (int i = i0; i < nw; i += stride) {
        float4 v = ((const float4*)wu)[i];
        ((uint4*)g_wut)[i] = make_uint4(f2tf(v.x), f2tf(v.y), f2tf(v.z), f2tf(v.w));
    }
    for (int i = i0; i < nw; i += stride) {
        float4 v = ((const float4*)wd)[i];
        ((uint4*)g_wdt)[i] = make_uint4(f2tf(v.x), f2tf(v.y), f2tf(v.z), f2tf(v.w));
    }
}

__global__ void router_kernel(const float* __restrict__ x,
                              const float* __restrict__ Wr) {
    __shared__ double s_ps[E_EXP];
    __shared__ double s_zs;
    int tid = threadIdx.x;
    if (tid < E_EXP) s_ps[tid] = 0.0;
    if (tid == 0) s_zs = 0.0;
    __syncthreads();
    int lane = tid & 31, warp = tid >> 5;
    int nw = (gridDim.x * blockDim.x) >> 5;
    int gw = blockIdx.x * (blockDim.x >> 5) + warp;
    double lps[E_EXP];
#pragma unroll
    for (int e = 0; e < E_EXP; e++) lps[e] = 0.0;
    double lzs = 0.0;
    for (int t = gw; t < T_TOK; t += nw) {
        const float* xr = x + (size_t)t * D_DIM;
        float acc[E_EXP];
#pragma unroll
        for (int e = 0; e < E_EXP; e++) acc[e] = 0.f;
        for (int i = lane; i < D_DIM; i += 32) {
            float xv = xr[i];
#pragma unroll
            for (int e = 0; e < E_EXP; e++)
                acc[e] = fmaf(xv, Wr[i * E_EXP + e], acc[e]);
        }
#pragma unroll
        for (int e = 0; e < E_EXP; e++)
#pragma unroll
            for (int o = 16; o > 0; o >>= 1)
                acc[e] += __shfl_xor_sync(0xffffffffu, acc[e], o);
        if (lane == 0) {
            float m = acc[0];
#pragma unroll
            for (int e = 1; e < E_EXP; e++) m = fmaxf(m, acc[e]);
            float s = 0.f, p[E_EXP];
#pragma unroll
            for (int e = 0; e < E_EXP; e++) { p[e] = expf(acc[e] - m); s += p[e]; }
            float inv = 1.f / s;
#pragma unroll
            for (int e = 0; e < E_EXP; e++) { p[e] *= inv; lps[e] += (double)p[e]; }
            float lse = m + logf(s);
            lzs += (double)lse * (double)lse;
            int i0 = 0; float v0 = acc[0];
#pragma unroll
            for (int e = 1; e < E_EXP; e++) if (acc[e] > v0) { v0 = acc[e]; i0 = e; }
            int i1 = -1; float v1 = -INFINITY;
#pragma unroll
            for (int e = 0; e < E_EXP; e++)
                if (e != i0 && acc[e] > v1) { v1 = acc[e]; i1 = e; }
            float rinv = 1.f / (p[i0] + p[i1]);
            int p0 = atomicAdd(&g_cnt[i0], 1);
            g_tok[i0 * CAP + p0] = t; g_wt[i0 * CAP + p0] = p[i0] * rinv;
            g_smap[t * 2 + 0] = i0 * CAP + p0;
            int p1 = atomicAdd(&g_cnt[i1], 1);
            g_tok[i1 * CAP + p1] = t; g_wt[i1 * CAP + p1] = p[i1] * rinv;
            g_smap[t * 2 + 1] = i1 * CAP + p1;
        }
    }
    if (lane == 0) {
#pragma unroll
        for (int e = 0; e < E_EXP; e++) atomicAdd(&s_ps[e], lps[e]);
        atomicAdd(&s_zs, lzs);
    }
    __syncthreads();
    if (tid < E_EXP) atomicAdd(&g_psum[tid], s_ps[tid]);
    if (tid == 0) atomicAdd(&g_zsum, s_zs);
}

__global__ void finalize_kernel(float* __restrict__ out, long long out_elems) {
    if (threadIdx.x == 0 && blockIdx.x == 0) {
        double lb = 0.0;
        for (int e = 0; e < E_EXP; e++)
            lb += ((double)g_cnt[e] / (double)(T_TOK * KSEL)) * (g_psum[e] / (double)T_TOK);
        lb *= (double)E_EXP;
        double aux = 0.01 * lb + 0.001 * (g_zsum / (double)T_TOK);
        long long idx = (long long)T_TOK * D_DIM;
        if (out_elems > idx) out[idx] = (float)aux;
    }
}

__global__ void combine_kernel(float* __restrict__ out) {
    int t = blockIdx.x;
    int d4 = threadIdx.x;
    int s0 = g_smap[t * 2 + 0], s1 = g_smap[t * 2 + 1];
    float w0 = g_wt[s0], w1 = g_wt[s1];
    float4 y0 = ((const float4*)g_Y)[(size_t)s0 * (D_DIM / 4) + d4];
    float4 y1 = ((const float4*)g_Y)[(size_t)s1 * (D_DIM / 4) + d4];
    float4 r;
    r.x = w0 * y0.x + w1 * y1.x;
    r.y = w0 * y0.y + w1 * y1.y;
    r.z = w0 * y0.z + w1 * y1.z;
    r.w = w0 * y0.w + w1 * y1.w;
    ((float4*)out)[(size_t)t * (D_DIM / 4) + d4] = r;
}

// ---------------- GEMM1: 256 thr, warp grid 2x4, warp tile 64x32, 3-stage ----------------
__global__ __launch_bounds__(256, 1)
void gemm1_mma(const float* dummy) {
    int e = blockIdx.z;
    int n = g_cnt[e];
    int row0 = blockIdx.y * 128;
    if (row0 >= n) return;
    int col0 = blockIdx.x * 128;

    extern __shared__ char smem[];
    int* toks = (int*)smem;
    uint32_t sb = s2u(smem);
    int tid = threadIdx.x, wid = tid >> 5, l = tid & 31;

    if (tid < 128) {
        int r = row0 + tid;
        toks[tid] = (r < n) ? g_tok[e * CAP + r] : g_tok[e * CAP];
    }
    __syncthreads();

    int arow = tid >> 1;
    int aseg0 = (tid & 1) * 4;
    int tok = toks[arow];
    const uint32_t* srcA = g_xt + (size_t)tok * D_DIM + aseg0 * 4;
    int brow = tid >> 3, bseg = tid & 7;
    const uint32_t* srcG = g_wgt + (size_t)e * D_DIM * F_DIM + (size_t)brow * F_DIM + col0 + bseg * 4;
    const uint32_t* srcU = g_wut + (size_t)e * D_DIM * F_DIM + (size_t)brow * F_DIM + col0 + bseg * 4;
    uint32_t adst[4], bdst[4];
#pragma unroll
    for (int j = 0; j < 4; j++) {
        adst[j] = (uint32_t)((arow * SA + (aseg0 + j) * 4) * 4);
        bdst[j] = (uint32_t)((brow * SB + bseg * 4 + j * 32) * 4);
    }

    const int NT = D_DIM / 32;  // 32

#define G1_ISSUE(c, slot) do { \
    uint32_t base_ = sb + BUF0 + (slot) * STAGE1; \
    int k0_ = (c) * 32; \
    const uint32_t* sa_ = srcA + k0_; \
    const uint32_t* sg_ = srcG + (size_t)k0_ * F_DIM; \
    const uint32_t* su_ = srcU + (size_t)k0_ * F_DIM; \
    CPA16(base_ + adst[0], sa_); \
    CPA16(base_ + adst[1], sa_ + 4); \
    CPA16(base_ + adst[2], sa_ + 8); \
    CPA16(base_ + adst[3], sa_ + 12); \
    CPA16(base_ + ABYTES + bdst[0], sg_); \
    CPA16(base_ + ABYTES + bdst[1], sg_ + 32); \
    CPA16(base_ + ABYTES + bdst[2], sg_ + 64); \
    CPA16(base_ + ABYTES + bdst[3], sg_ + 96); \
    CPA16(base_ + ABYTES + BBYTES + bdst[0], su_); \
    CPA16(base_ + ABYTES + BBYTES + bdst[1], su_ + 32); \
    CPA16(base_ + ABYTES + BBYTES + bdst[2], su_ + 64); \
    CPA16(base_ + ABYTES + BBYTES + bdst[3], su_ + 96); \
} while (0)

    float accG[4][4][4] = {}, accU[4][4][4] = {};
    int wm = wid & 1, wn = wid >> 1;
    int qr = l >> 2, qc = l & 3;

    G1_ISSUE(0, 0); CPCOMMIT();
    G1_ISSUE(1, 1); CPCOMMIT();

    int slot = 0;
#pragma unroll 1
    for (int c = 0; c < NT; c++) {
        CPWAITG(1);
        __syncthreads();
        const uint32_t* As = (const uint32_t*)(smem + BUF0 + slot * STAGE1);
        const uint32_t* Gs = As + ABYTES / 4;
        const uint32_t* Us = As + (ABYTES + BBYTES) / 4;
#pragma unroll
        for (int ks = 0; ks < 4; ks++) {
            int kk = ks * 8;
            uint32_t af[4][4];
#pragma unroll
            for (int mt = 0; mt < 4; mt++) {
                int r0 = wm * 64 + mt * 16 + qr;
                af[mt][0] = As[r0 * SA + kk + qc];
                af[mt][1] = As[(r0 + 8) * SA + kk + qc];
                af[mt][2] = As[r0 * SA + kk + qc + 4];
                af[mt][3] = As[(r0 + 8) * SA + kk + qc + 4];
            }
            uint32_t bg[4][2], bu[4][2];
#pragma unroll
            for (int nt = 0; nt < 4; nt++) {
                int cc = wn * 32 + nt * 8 + qr;
                bg[nt][0] = Gs[(kk + qc) * SB + cc];
                bg[nt][1] = Gs[(kk + qc + 4) * SB + cc];
                bu[nt][0] = Us[(kk + qc) * SB + cc];
                bu[nt][1] = Us[(kk + qc + 4) * SB + cc];
            }
#pragma unroll
            for (int mt = 0; mt < 4; mt++)
#pragma unroll
                for (int nt = 0; nt < 4; nt++) {
                    mma8(accG[mt][nt], af[mt], bg[nt]);
                    mma8(accU[mt][nt], af[mt], bu[nt]);
                }
        }
        if (c + 2 < NT) {
            int ws = slot + 2; if (ws >= NSTG) ws -= NSTG;
            G1_ISSUE(c + 2, ws);
        }
        CPCOMMIT();
        if (++slot == NSTG) slot = 0;
    }

#pragma unroll
    for (int mt = 0; mt < 4; mt++)
#pragma unroll
        for (int half = 0; half < 2; half++) {
            int grow = row0 + wm * 64 + mt * 16 + qr + half * 8;
            if (grow < n) {
                float* hrow = &g_H[((size_t)e * CAP + grow) * F_DIM + col0];
#pragma unroll
                for (int nt = 0; nt < 4; nt++) {
                    float g0 = accG[mt][nt][half * 2], g1 = accG[mt][nt][half * 2 + 1];
                    float u0 = accU[mt][nt][half * 2], u1 = accU[mt][nt][half * 2 + 1];
                    float h0 = __uint_as_float(f2tf(g0 / (1.f + expf(-g0)) * u0));
                    float h1 = __uint_as_float(f2tf(g1 / (1.f + expf(-g1)) * u1));
                    *(float2*)(hrow + wn * 32 + nt * 8 + qc * 2) = make_float2(h0, h1);
                }
            }
        }
}

// ---------------- GEMM2: Y[slot] = H[slot] @ Wd — 3-stage, no atomics ----------------
__global__ __launch_bounds__(256, 1)
void gemm2_mma(const float* dummy) {
    int e = blockIdx.z;
    int n = g_cnt[e];
    int row0 = blockIdx.y * 128;
    if (row0 >= n) return;
    int col0 = blockIdx.x * 128;

    extern __shared__ char smem[];
    uint32_t sb = s2u(smem);
    int tid = threadIdx.x, wid = tid >> 5, l = tid & 31;

    int arow = tid >> 1;
    int aseg0 = (tid & 1) * 4;
    int hr = (row0 + arow < n) ? (row0 + arow) : 0;
    const uint32_t* srcA = (const uint32_t*)g_H + ((size_t)e * CAP + hr) * F_DIM + aseg0 * 4;
    int brow = tid >> 3, bseg = tid & 7;
    const uint32_t* srcB = g_wdt + (size_t)e * F_DIM * D_DIM + (size_t)brow * D_DIM + col0 + bseg * 4;
    uint32_t adst[4], bdst[4];
#pragma unroll
    for (int j = 0; j < 4; j++) {
        adst[j] = (uint32_t)((arow * SA + (aseg0 + j) * 4) * 4);
        bdst[j] = (uint32_t)((brow * SB + bseg * 4 + j * 32) * 4);
    }

    const int NT = F_DIM / 32;  // 64

#define G2_ISSUE(c, slot) do { \
    uint32_t base_ = sb + BUF0 + (slot) * STAGE2; \
    int k0_ = (c) * 32; \
    const uint32_t* sa_ = srcA + k0_; \
    const uint32_t* sb_ = srcB + (size_t)k0_ * D_DIM; \
    CPA16(base_ + adst[0], sa_); \
    CPA16(base_ + adst[1], sa_ + 4); \
    CPA16(base_ + adst[2], sa_ + 8); \
    CPA16(base_ + adst[3], sa_ + 12); \
    CPA16(base_ + ABYTES + bdst[0], sb_); \
    CPA16(base_ + ABYTES + bdst[1], sb_ + 32); \
    CPA16(base_ + ABYTES + bdst[2], sb_ + 64); \
    CPA16(base_ + ABYTES + bdst[3], sb_ + 96); \
} while (0)

    float acc[4][4][4] = {};
    int wm = wid & 1, wn = wid >> 1;
    int qr = l >> 2, qc = l & 3;

    G2_ISSUE(0, 0); CPCOMMIT();
    G2_ISSUE(1, 1); CPCOMMIT();

    int slot = 0;
#pragma unroll 1
    for (int c = 0; c < NT; c++) {
        CPWAITG(1);
        __syncthreads();
        const uint32_t* As = (const uint32_t*)(smem + BUF0 + slot * STAGE2);
        const uint32_t* Bs = As + ABYTES / 4;
#pragma unroll
        for (int ks = 0; ks < 4; ks++) {
            int kk = ks * 8;
            uint32_t af[4][4];
#pragma unroll
            for (int mt = 0; mt < 4; mt++) {
                int r0 = wm * 64 + mt * 16 + qr;
                af[mt][0] = As[r0 * SA + kk + qc];
                af[mt][1] = As[(r0 + 8) * SA + kk + qc];
                af[mt][2] = As[r0 * SA + kk + qc + 4];
                af[mt][3] = As[(r0 + 8) * SA + kk + qc + 4];
            }
            uint32_t bf[4][2];
#pragma unroll
            for (int nt = 0; nt < 4; nt++) {
                int cc = wn * 32 + nt * 8 + qr;
                bf[nt][0] = Bs[(kk + qc) * SB + cc];
                bf[nt][1] = Bs[(kk + qc + 4) * SB + cc];
            }
#pragma unroll
            for (int mt = 0; mt < 4; mt++)
#pragma unroll
                for (int nt = 0; nt < 4; nt++)
                    mma8(acc[mt][nt], af[mt], bf[nt]);
        }
        if (c + 2 < NT) {
            int ws = slot + 2; if (ws >= NSTG) ws -= NSTG;
            G2_ISSUE(c + 2, ws);
        }
        CPCOMMIT();
        if (++slot == NSTG) slot = 0;
    }

#pragma unroll
    for (int mt = 0; mt < 4; mt++)
#pragma unroll
        for (int half = 0; half < 2; half++) {
            int grow = row0 + wm * 64 + mt * 16 + qr + half * 8;
            if (grow < n) {
                float* yrow = &g_Y[((size_t)e * CAP + grow) * D_DIM + col0];
#pragma unroll
                for (int nt = 0; nt < 4; nt++) {
                    float v0 = acc[mt][nt][half * 2];
                    float v1 = acc[mt][nt][half * 2 + 1];
                    *(float2*)(yrow + wn * 32 + nt * 8 + qc * 2) = make_float2(v0, v1);
                }
            }
        }
}

// ---------------- launch ----------------
extern "C" void kernel_launch(void* const* d_in, const int* in_sizes, int n_in,
                              void* d_out, int out_size) {
    const float* x  = (const float*)d_in[0];
    const float* Wr = (const float*)d_in[1];
    const float* Wg = (const float*)d_in[2];
    const float* Wu = (const float*)d_in[3];
    const float* Wd = (const float*)d_in[4];
    float* out = (float*)d_out;

    cudaFuncSetAttribute(gemm1_mma, cudaFuncAttributeMaxDynamicSharedMemorySize, SMEM1);
    cudaFuncSetAttribute(gemm2_mma, cudaFuncAttributeMaxDynamicSharedMemorySize, SMEM2);

    init_kernel<<<1, 32>>>();
    cvt_all<<<2048, 256>>>(x, Wg, Wu, Wd);
    router_kernel<<<128, 256>>>(x, Wr);
    dim3 g1(F_DIM / 128, CAP / 128, E_EXP);
    gemm1_mma<<<g1, 256, SMEM1>>>(x);
    dim3 g2(D_DIM / 128, CAP / 128, E_EXP);
    gemm2_mma<<<g2, 256, SMEM2>>>(x);
    combine_kernel<<<T_TOK, D_DIM / 4>>>(out);
    finalize_kernel<<<1, 32>>>(out, (long long)out_size);
}

// round 11
// speedup vs baseline: 1.4579x; 1.0350x over previous
#include <cuda_runtime.h>
#include <cstdint>
#include <math.h>

#define T_TOK 8192
#define D_DIM 1024
#define F_DIM 2048
#define E_EXP 8
#define KSEL  2
#define CAP   4096

// ---------------- device scratch ----------------
__device__ float    g_H  [(size_t)E_EXP * CAP * F_DIM];
__device__ float    g_Y  [(size_t)E_EXP * CAP * D_DIM];
__device__ uint32_t g_xt [(size_t)T_TOK * D_DIM];
__device__ uint32_t g_wgt[(size_t)E_EXP * D_DIM * F_DIM];
__device__ uint32_t g_wut[(size_t)E_EXP * D_DIM * F_DIM];
__device__ uint32_t g_wdt[(size_t)E_EXP * F_DIM * D_DIM];
__device__ int      g_cnt[E_EXP];
__device__ int      g_tok[E_EXP * CAP];
__device__ float    g_wt [E_EXP * CAP];
__device__ int      g_smap[T_TOK * KSEL];
__device__ double   g_psum[E_EXP];
__device__ double   g_zsum;

// ---------------- helpers ----------------
__device__ __forceinline__ uint32_t f2tf(float f) {
    uint32_t r;
    asm("cvt.rna.tf32.f32 %0, %1;" : "=r"(r) : "f"(f));
    return r;
}
__device__ __forceinline__ uint32_t s2u(const void* p) {
    uint32_t a;
    asm("{ .reg .u64 t; cvta.to.shared.u64 t, %1; cvt.u32.u64 %0, t; }" : "=r"(a) : "l"(p));
    return a;
}
#define CPA16(dst, src) \
    asm volatile("cp.async.cg.shared.global [%0], [%1], 16;" :: "r"((uint32_t)(dst)), "l"(src) : "memory")
#define CPCOMMIT() asm volatile("cp.async.commit_group;" ::: "memory")
#define CPWAITG(n) asm volatile("cp.async.wait_group %0;" :: "n"(n) : "memory")

__device__ __forceinline__ void mma8(float* d, const uint32_t* a, const uint32_t* b) {
    asm volatile("mma.sync.aligned.m16n8k8.row.col.f32.tf32.tf32.f32 "
                 "{%0,%1,%2,%3}, {%4,%5,%6,%7}, {%8,%9}, {%0,%1,%2,%3};"
                 : "+f"(d[0]), "+f"(d[1]), "+f"(d[2]), "+f"(d[3])
                 : "r"(a[0]), "r"(a[1]), "r"(a[2]), "r"(a[3]), "r"(b[0]), "r"(b[1]));
}

// SMEM strides (words). SB=136 / SB2=264: fragment-load banks = (8*qc + qr + 8*nt [+64*wn]) mod 32
// -> all 32 lanes distinct, conflict-free.
#define SA 36
#define SB 136
#define SB2 264
#define ABYTES  (128 * SA * 4)          // 18432
#define BBYTES  (32 * SB * 4)           // 17408
#define BBYTES2 (32 * SB2 * 4)          // 33792
#define STAGE1 (ABYTES + 2 * BBYTES)    // 53248
#define STAGE2 (ABYTES + BBYTES2)       // 52224
#define BUF0   1024
#define NSTG   3
#define SMEM1  (BUF0 + NSTG * STAGE1)   // 160768
#define SMEM2  (BUF0 + NSTG * STAGE2)   // 157696

// ---------------- small kernels ----------------
__global__ void init_kernel() {
    int i = threadIdx.x;
    if (i < E_EXP) { g_cnt[i] = 0; g_psum[i] = 0.0; }
    if (i == 0) g_zsum = 0.0;
}

__global__ void cvt_all(const float* __restrict__ x, const float* __restrict__ wg,
                        const float* __restrict__ wu, const float* __restrict__ wd) {
    int stride = gridDim.x * blockDim.x;
    int i0 = blockIdx.x * blockDim.x + threadIdx.x;
    const int nx = T_TOK * D_DIM / 4;
    const int nw = E_EXP * D_DIM * F_DIM / 4;
    for (int i = i0; i < nx; i += stride) {
        float4 v = ((const float4*)x)[i];
        ((uint4*)g_xt)[i] = make_uint4(f2tf(v.x), f2tf(v.y), f2tf(v.z), f2tf(v.w));
    }
    for (int i = i0; i < nw; i += stride) {
        float4 v = ((const float4*)wg)[i];
        ((uint4*)g_wgt)[i] = make_uint4(f2tf(v.x), f2tf(v.y), f2tf(v.z), f2tf(v.w));
    }
    for (int i = i0; i < nw; i += stride) {
        float4 v = ((const float4*)wu)[i];
        ((uint4*)g_wut)[i] = make_uint4(f2tf(v.x), f2tf(v.y), f2tf(v.z), f2tf(v.w));
    }
    for (int i = i0; i < nw; i += stride) {
        float4 v = ((const float4*)wd)[i];
        ((uint4*)g_wdt)[i] = make_uint4(f2tf(v.x), f2tf(v.y), f2tf(v.z), f2tf(v.w));
    }
}

__global__ void router_kernel(const float* __restrict__ x,
                              const float* __restrict__ Wr) {
    __shared__ double s_ps[E_EXP];
    __shared__ double s_zs;
    int tid = threadIdx.x;
    if (tid < E_EXP) s_ps[tid] = 0.0;
    if (tid == 0) s_zs = 0.0;
    __syncthreads();
    int lane = tid & 31, warp = tid >> 5;
    int nw = (gridDim.x * blockDim.x) >> 5;
    int gw = blockIdx.x * (blockDim.x >> 5) + warp;
    double lps[E_EXP];
#pragma unroll
    for (int e = 0; e < E_EXP; e++) lps[e] = 0.0;
    double lzs = 0.0;
    for (int t = gw; t < T_TOK; t += nw) {
        const float* xr = x + (size_t)t * D_DIM;
        float acc[E_EXP];
#pragma unroll
        for (int e = 0; e < E_EXP; e++) acc[e] = 0.f;
        for (int i = lane; i < D_DIM; i += 32) {
            float xv = xr[i];
#pragma unroll
            for (int e = 0; e < E_EXP; e++)
                acc[e] = fmaf(xv, Wr[i * E_EXP + e], acc[e]);
        }
#pragma unroll
        for (int e = 0; e < E_EXP; e++)
#pragma unroll
            for (int o = 16; o > 0; o >>= 1)
                acc[e] += __shfl_xor_sync(0xffffffffu, acc[e], o);
        if (lane == 0) {
            float m = acc[0];
#pragma unroll
            for (int e = 1; e < E_EXP; e++) m = fmaxf(m, acc[e]);
            float s = 0.f, p[E_EXP];
#pragma unroll
            for (int e = 0; e < E_EXP; e++) { p[e] = expf(acc[e] - m); s += p[e]; }
            float inv = 1.f / s;
#pragma unroll
            for (int e = 0; e < E_EXP; e++) { p[e] *= inv; lps[e] += (double)p[e]; }
            float lse = m + logf(s);
            lzs += (double)lse * (double)lse;
            int i0 = 0; float v0 = acc[0];
#pragma unroll
            for (int e = 1; e < E_EXP; e++) if (acc[e] > v0) { v0 = acc[e]; i0 = e; }
            int i1 = -1; float v1 = -INFINITY;
#pragma unroll
            for (int e = 0; e < E_EXP; e++)
                if (e != i0 && acc[e] > v1) { v1 = acc[e]; i1 = e; }
            float rinv = 1.f / (p[i0] + p[i1]);
            int p0 = atomicAdd(&g_cnt[i0], 1);
            g_tok[i0 * CAP + p0] = t; g_wt[i0 * CAP + p0] = p[i0] * rinv;
            g_smap[t * 2 + 0] = i0 * CAP + p0;
            int p1 = atomicAdd(&g_cnt[i1], 1);
            g_tok[i1 * CAP + p1] = t; g_wt[i1 * CAP + p1] = p[i1] * rinv;
            g_smap[t * 2 + 1] = i1 * CAP + p1;
        }
    }
    if (lane == 0) {
#pragma unroll
        for (int e = 0; e < E_EXP; e++) atomicAdd(&s_ps[e], lps[e]);
        atomicAdd(&s_zs, lzs);
    }
    __syncthreads();
    if (tid < E_EXP) atomicAdd(&g_psum[tid], s_ps[tid]);
    if (tid == 0) atomicAdd(&g_zsum, s_zs);
}

__global__ void finalize_kernel(float* __restrict__ out, long long out_elems) {
    if (threadIdx.x == 0 && blockIdx.x == 0) {
        double lb = 0.0;
        for (int e = 0; e < E_EXP; e++)
            lb += ((double)g_cnt[e] / (double)(T_TOK * KSEL)) * (g_psum[e] / (double)T_TOK);
        lb *= (double)E_EXP;
        double aux = 0.01 * lb + 0.001 * (g_zsum / (double)T_TOK);
        long long idx = (long long)T_TOK * D_DIM;
        if (out_elems > idx) out[idx] = (float)aux;
    }
}

__global__ void combine_kernel(float* __restrict__ out) {
    int t = blockIdx.x;
    int d4 = threadIdx.x;
    int s0 = g_smap[t * 2 + 0], s1 = g_smap[t * 2 + 1];
    float w0 = g_wt[s0], w1 = g_wt[s1];
    float4 y0 = ((const float4*)g_Y)[(size_t)s0 * (D_DIM / 4) + d4];
    float4 y1 = ((const float4*)g_Y)[(size_t)s1 * (D_DIM / 4) + d4];
    float4 r;
    r.x = w0 * y0.x + w1 * y1.x;
    r.y = w0 * y0.y + w1 * y1.y;
    r.z = w0 * y0.z + w1 * y1.z;
    r.w = w0 * y0.w + w1 * y1.w;
    ((float4*)out)[(size_t)t * (D_DIM / 4) + d4] = r;
}

// ---------------- GEMM1: 256 thr, warp grid 2x4, warp tile 64x32 (G+U), 3-stage ----------------
__global__ __launch_bounds__(256, 1)
void gemm1_mma(const float* dummy) {
    int e = blockIdx.z;
    int n = g_cnt[e];
    int row0 = blockIdx.y * 128;
    if (row0 >= n) return;
    int col0 = blockIdx.x * 128;

    extern __shared__ char smem[];
    int* toks = (int*)smem;
    uint32_t sb = s2u(smem);
    int tid = threadIdx.x, wid = tid >> 5, l = tid & 31;

    if (tid < 128) {
        int r = row0 + tid;
        toks[tid] = (r < n) ? g_tok[e * CAP + r] : g_tok[e * CAP];
    }
    __syncthreads();

    int arow = tid >> 1;
    int aseg0 = (tid & 1) * 4;
    int tok = toks[arow];
    const uint32_t* srcA = g_xt + (size_t)tok * D_DIM + aseg0 * 4;
    int brow = tid >> 3, bseg = tid & 7;
    const uint32_t* srcG = g_wgt + (size_t)e * D_DIM * F_DIM + (size_t)brow * F_DIM + col0 + bseg * 4;
    const uint32_t* srcU = g_wut + (size_t)e * D_DIM * F_DIM + (size_t)brow * F_DIM + col0 + bseg * 4;
    uint32_t adst[4], bdst[4];
#pragma unroll
    for (int j = 0; j < 4; j++) {
        adst[j] = (uint32_t)((arow * SA + (aseg0 + j) * 4) * 4);
        bdst[j] = (uint32_t)((brow * SB + bseg * 4 + j * 32) * 4);
    }

    const int NT = D_DIM / 32;  // 32

#define G1_ISSUE(c, slot) do { \
    uint32_t base_ = sb + BUF0 + (slot) * STAGE1; \
    int k0_ = (c) * 32; \
    const uint32_t* sa_ = srcA + k0_; \
    const uint32_t* sg_ = srcG + (size_t)k0_ * F_DIM; \
    const uint32_t* su_ = srcU + (size_t)k0_ * F_DIM; \
    CPA16(base_ + adst[0], sa_); \
    CPA16(base_ + adst[1], sa_ + 4); \
    CPA16(base_ + adst[2], sa_ + 8); \
    CPA16(base_ + adst[3], sa_ + 12); \
    CPA16(base_ + ABYTES + bdst[0], sg_); \
    CPA16(base_ + ABYTES + bdst[1], sg_ + 32); \
    CPA16(base_ + ABYTES + bdst[2], sg_ + 64); \
    CPA16(base_ + ABYTES + bdst[3], sg_ + 96); \
    CPA16(base_ + ABYTES + BBYTES + bdst[0], su_); \
    CPA16(base_ + ABYTES + BBYTES + bdst[1], su_ + 32); \
    CPA16(base_ + ABYTES + BBYTES + bdst[2], su_ + 64); \
    CPA16(base_ + ABYTES + BBYTES + bdst[3], su_ + 96); \
} while (0)

    float accG[4][4][4] = {}, accU[4][4][4] = {};
    int wm = wid & 1, wn = wid >> 1;
    int qr = l >> 2, qc = l & 3;

    G1_ISSUE(0, 0); CPCOMMIT();
    G1_ISSUE(1, 1); CPCOMMIT();

    int slot = 0;
#pragma unroll 1
    for (int c = 0; c < NT; c++) {
        CPWAITG(1);
        __syncthreads();
        const uint32_t* As = (const uint32_t*)(smem + BUF0 + slot * STAGE1);
        const uint32_t* Gs = As + ABYTES / 4;
        const uint32_t* Us = As + (ABYTES + BBYTES) / 4;
#pragma unroll
        for (int ks = 0; ks < 4; ks++) {
            int kk = ks * 8;
            uint32_t af[4][4];
#pragma unroll
            for (int mt = 0; mt < 4; mt++) {
                int r0 = wm * 64 + mt * 16 + qr;
                af[mt][0] = As[r0 * SA + kk + qc];
                af[mt][1] = As[(r0 + 8) * SA + kk + qc];
                af[mt][2] = As[r0 * SA + kk + qc + 4];
                af[mt][3] = As[(r0 + 8) * SA + kk + qc + 4];
            }
            uint32_t bg[4][2], bu[4][2];
#pragma unroll
            for (int nt = 0; nt < 4; nt++) {
                int cc = wn * 32 + nt * 8 + qr;
                bg[nt][0] = Gs[(kk + qc) * SB + cc];
                bg[nt][1] = Gs[(kk + qc + 4) * SB + cc];
                bu[nt][0] = Us[(kk + qc) * SB + cc];
                bu[nt][1] = Us[(kk + qc + 4) * SB + cc];
            }
#pragma unroll
            for (int mt = 0; mt < 4; mt++)
#pragma unroll
                for (int nt = 0; nt < 4; nt++) {
                    mma8(accG[mt][nt], af[mt], bg[nt]);
                    mma8(accU[mt][nt], af[mt], bu[nt]);
                }
        }
        if (c + 2 < NT) {
            int ws = slot + 2; if (ws >= NSTG) ws -= NSTG;
            G1_ISSUE(c + 2, ws);
        }
        CPCOMMIT();
        if (++slot == NSTG) slot = 0;
    }

#pragma unroll
    for (int mt = 0; mt < 4; mt++)
#pragma unroll
        for (int half = 0; half < 2; half++) {
            int grow = row0 + wm * 64 + mt * 16 + qr + half * 8;
            if (grow < n) {
                float* hrow = &g_H[((size_t)e * CAP + grow) * F_DIM + col0];
#pragma unroll
                for (int nt = 0; nt < 4; nt++) {
                    float g0 = accG[mt][nt][half * 2], g1 = accG[mt][nt][half * 2 + 1];
                    float u0 = accU[mt][nt][half * 2], u1 = accU[mt][nt][half * 2 + 1];
                    float h0 = __uint_as_float(f2tf(g0 / (1.f + expf(-g0)) * u0));
                    float h1 = __uint_as_float(f2tf(g1 / (1.f + expf(-g1)) * u1));
                    *(float2*)(hrow + wn * 32 + nt * 8 + qc * 2) = make_float2(h0, h1);
                }
            }
        }
}

// ---------------- GEMM2: warp tile 64x64, CTA 128x256, 3-stage ----------------
__global__ __launch_bounds__(256, 1)
void gemm2_mma(const float* dummy) {
    int e = blockIdx.z;
    int n = g_cnt[e];
    int row0 = blockIdx.y * 128;
    if (row0 >= n) return;
    int col0 = blockIdx.x * 256;

    extern __shared__ char smem[];
    uint32_t sb = s2u(smem);
    int tid = threadIdx.x, wid = tid >> 5, l = tid & 31;

    int arow = tid >> 1;
    int aseg0 = (tid & 1) * 4;
    int hr = (row0 + arow < n) ? (row0 + arow) : 0;
    const uint32_t* srcA = (const uint32_t*)g_H + ((size_t)e * CAP + hr) * F_DIM + aseg0 * 4;
    int brow = tid >> 3, bseg = tid & 7;
    const uint32_t* srcB = g_wdt + (size_t)e * F_DIM * D_DIM + (size_t)brow * D_DIM + col0 + bseg * 4;
    uint32_t adst[4], bdst[8];
#pragma unroll
    for (int j = 0; j < 4; j++)
        adst[j] = (uint32_t)((arow * SA + (aseg0 + j) * 4) * 4);
#pragma unroll
    for (int j = 0; j < 8; j++)
        bdst[j] = (uint32_t)((brow * SB2 + bseg * 4 + j * 32) * 4);

    const int NT = F_DIM / 32;  // 64

#define G2_ISSUE(c, slot) do { \
    uint32_t base_ = sb + BUF0 + (slot) * STAGE2; \
    int k0_ = (c) * 32; \
    const uint32_t* sa_ = srcA + k0_; \
    const uint32_t* sb_ = srcB + (size_t)k0_ * D_DIM; \
    CPA16(base_ + adst[0], sa_); \
    CPA16(base_ + adst[1], sa_ + 4); \
    CPA16(base_ + adst[2], sa_ + 8); \
    CPA16(base_ + adst[3], sa_ + 12); \
    CPA16(base_ + ABYTES + bdst[0], sb_); \
    CPA16(base_ + ABYTES + bdst[1], sb_ + 32); \
    CPA16(base_ + ABYTES + bdst[2], sb_ + 64); \
    CPA16(base_ + ABYTES + bdst[3], sb_ + 96); \
    CPA16(base_ + ABYTES + bdst[4], sb_ + 128); \
    CPA16(base_ + ABYTES + bdst[5], sb_ + 160); \
    CPA16(base_ + ABYTES + bdst[6], sb_ + 192); \
    CPA16(base_ + ABYTES + bdst[7], sb_ + 224); \
} while (0)

    float acc[4][8][4] = {};
    int wm = wid & 1, wn = wid >> 1;   // wm: 2 x 64 rows, wn: 4 x 64 cols
    int qr = l >> 2, qc = l & 3;

    G2_ISSUE(0, 0); CPCOMMIT();
    G2_ISSUE(1, 1); CPCOMMIT();

    int slot = 0;
#pragma unroll 1
    for (int c = 0; c < NT; c++) {
        CPWAITG(1);
        __syncthreads();
        const uint32_t* As = (const uint32_t*)(smem + BUF0 + slot * STAGE2);
        const uint32_t* Bs = As + ABYTES / 4;
#pragma unroll
        for (int ks = 0; ks < 4; ks++) {
            int kk = ks * 8;
            uint32_t af[4][4];
#pragma unroll
            for (int mt = 0; mt < 4; mt++) {
                int r0 = wm * 64 + mt * 16 + qr;
                af[mt][0] = As[r0 * SA + kk + qc];
                af[mt][1] = As[(r0 + 8) * SA + kk + qc];
                af[mt][2] = As[r0 * SA + kk + qc + 4];
                af[mt][3] = As[(r0 + 8) * SA + kk + qc + 4];
            }
            uint32_t bf[8][2];
#pragma unroll
            for (int nt = 0; nt < 8; nt++) {
                int cc = wn * 64 + nt * 8 + qr;
                bf[nt][0] = Bs[(kk + qc) * SB2 + cc];
                bf[nt][1] = Bs[(kk + qc + 4) * SB2 + cc];
            }
#pragma unroll
            for (int mt = 0; mt < 4; mt++)
#pragma unroll
                for (int nt = 0; nt < 8; nt++)
                    mma8(acc[mt][nt], af[mt], bf[nt]);
        }
        if (c + 2 < NT) {
            int ws = slot + 2; if (ws >= NSTG) ws -= NSTG;
            G2_ISSUE(c + 2, ws);
        }
        CPCOMMIT();
        if (++slot == NSTG) slot = 0;
    }

#pragma unroll
    for (int mt = 0; mt < 4; mt++)
#pragma unroll
        for (int half = 0; half < 2; half++) {
            int grow = row0 + wm * 64 + mt * 16 + qr + half * 8;
            if (grow < n) {
                float* yrow = &g_Y[((size_t)e * CAP + grow) * D_DIM + col0];
#pragma unroll
                for (int nt = 0; nt < 8; nt++) {
                    float v0 = acc[mt][nt][half * 2];
                    float v1 = acc[mt][nt][half * 2 + 1];
                    *(float2*)(yrow + wn * 64 + nt * 8 + qc * 2) = make_float2(v0, v1);
                }
            }
        }
}

// ---------------- launch ----------------
extern "C" void kernel_launch(void* const* d_in, const int* in_sizes, int n_in,
                              void* d_out, int out_size) {
    const float* x  = (const float*)d_in[0];
    const float* Wr = (const float*)d_in[1];
    const float* Wg = (const float*)d_in[2];
    const float* Wu = (const float*)d_in[3];
    const float* Wd = (const float*)d_in[4];
    float* out = (float*)d_out;

    cudaFuncSetAttribute(gemm1_mma, cudaFuncAttributeMaxDynamicSharedMemorySize, SMEM1);
    cudaFuncSetAttribute(gemm2_mma, cudaFuncAttributeMaxDynamicSharedMemorySize, SMEM2);

    init_kernel<<<1, 32>>>();
    cvt_all<<<2048, 256>>>(x, Wg, Wu, Wd);
    router_kernel<<<128, 256>>>(x, Wr);
    dim3 g1(F_DIM / 128, CAP / 128, E_EXP);
    gemm1_mma<<<g1, 256, SMEM1>>>(x);
    dim3 g2(D_DIM / 256, CAP / 128, E_EXP);
    gemm2_mma<<<g2, 256, SMEM2>>>(x);
    combine_kernel<<<T_TOK, D_DIM / 4>>>(out);
    finalize_kernel<<<1, 32>>>(out, (long long)out_size);
}